// round 1
// baseline (speedup 1.0000x reference)
#include <cuda_runtime.h>
#include <math.h>

// Problem constants (MoDRouter_48387101556956: fixed shapes)
#define BB   4
#define NN   4096
#define DD   1024
#define DFFN 4096
#define KK   2048
#define MM   (BB * KK)   // 8192 selected tokens total

// ---------------------------------------------------------------------------
// Device scratch (no allocations allowed in kernel_launch)
// ---------------------------------------------------------------------------
__device__ float g_scores[BB * NN];
__device__ int   g_sel[BB * KK];                    // selected token index (0..NN-1) per batch
__device__ float g_h[(size_t)MM * DFFN];            // GELU(x_sel @ w1 + b1), 128 MiB

// ---------------------------------------------------------------------------
// 1) Gate scores: scores[b,n] = dot(x[b,n,:], gate_w)  — one warp per row
// ---------------------------------------------------------------------------
__global__ void scores_kernel(const float* __restrict__ x,
                              const float* __restrict__ gw) {
    int gwarp = (blockIdx.x * blockDim.x + threadIdx.x) >> 5;
    int lane  = threadIdx.x & 31;
    if (gwarp >= BB * NN) return;
    const float4* xr = reinterpret_cast<const float4*>(x + (size_t)gwarp * DD);
    const float4* g4 = reinterpret_cast<const float4*>(gw);
    float s = 0.0f;
#pragma unroll
    for (int i = 0; i < DD / 4 / 32; ++i) {   // 8 float4 per lane
        float4 a = xr[lane + i * 32];
        float4 b = g4[lane + i * 32];
        s += a.x * b.x + a.y * b.y + a.z * b.z + a.w * b.w;
    }
#pragma unroll
    for (int o = 16; o; o >>= 1) s += __shfl_xor_sync(0xFFFFFFFFu, s, o);
    if (lane == 0) g_scores[gwarp] = s;
}

// ---------------------------------------------------------------------------
// 2) Per-batch top-K: bitonic sort 4096 (score,idx) pairs in smem (ascending),
//    take the last K indices. Order within the set is irrelevant downstream.
// ---------------------------------------------------------------------------
__global__ void topk_kernel() {
    __shared__ float key[NN];
    __shared__ int   val[NN];
    int b = blockIdx.x;
    for (int i = threadIdx.x; i < NN; i += blockDim.x) {
        key[i] = g_scores[b * NN + i];
        val[i] = i;
    }
    __syncthreads();
    for (int k = 2; k <= NN; k <<= 1) {
        for (int j = k >> 1; j > 0; j >>= 1) {
            for (int i = threadIdx.x; i < NN; i += blockDim.x) {
                int ixj = i ^ j;
                if (ixj > i) {
                    bool up = ((i & k) == 0);
                    float ki = key[i], kj = key[ixj];
                    bool do_swap = up ? (ki > kj) : (ki < kj);
                    if (do_swap) {
                        key[i] = kj; key[ixj] = ki;
                        int t = val[i]; val[i] = val[ixj]; val[ixj] = t;
                    }
                }
            }
            __syncthreads();
        }
    }
    for (int i = threadIdx.x; i < KK; i += blockDim.x)
        g_sel[b * KK + i] = val[NN - 1 - i];
}

// ---------------------------------------------------------------------------
// 3) out = x (full copy); selected rows get overwritten by ffn2 scatter
// ---------------------------------------------------------------------------
__global__ void copy_kernel(const float* __restrict__ x, float* __restrict__ out) {
    size_t n4 = (size_t)BB * NN * DD / 4;
    const float4* src = reinterpret_cast<const float4*>(x);
    float4*       dst = reinterpret_cast<float4*>(out);
    for (size_t i = blockIdx.x * (size_t)blockDim.x + threadIdx.x; i < n4;
         i += (size_t)gridDim.x * blockDim.x)
        dst[i] = src[i];
}

// ---------------------------------------------------------------------------
// SGEMM tiling: 128x128 block tile, K=8 step, 256 threads, 8x8 micro-tile
// ---------------------------------------------------------------------------
#define BM 128
#define BN 128
#define BK 8
#define TM 8
#define TN 8

__device__ __forceinline__ float gelu_tanh(float u) {
    float t = tanhf(0.7978845608028654f * (u + 0.044715f * u * u * u));
    return 0.5f * u * (1.0f + t);
}

// 4) GEMM1 (gathered A) + bias + GELU:  g_h = gelu(x[sel] @ w1 + b1)
__global__ __launch_bounds__(256, 2)
void ffn1_kernel(const float* __restrict__ x,
                 const float* __restrict__ w1,
                 const float* __restrict__ b1) {
    __shared__ float    As[BK][BM];
    __shared__ float    Bs[BK][BN];
    __shared__ unsigned rowtok[BM];   // (b*NN + tok) for each local row

    int mt = blockIdx.y, nt = blockIdx.x;
    int tid = threadIdx.x;
    if (tid < BM) {
        int m = mt * BM + tid;
        int b = m / KK, j = m % KK;
        rowtok[tid] = (unsigned)(b * NN + g_sel[b * KK + j]);
    }
    __syncthreads();

    int tx = tid % 16, ty = tid / 16;
    int arow = tid >> 1, acol = (tid & 1) * 4;
    int brow = tid >> 5, bcol = (tid & 31) * 4;

    float acc[TM][TN] = {};
    const float* Bp = w1 + nt * BN;
    size_t abase = (size_t)rowtok[arow] * DD;

    for (int k0 = 0; k0 < DD; k0 += BK) {
        float4 av = *reinterpret_cast<const float4*>(x + abase + k0 + acol);
        As[acol + 0][arow] = av.x;
        As[acol + 1][arow] = av.y;
        As[acol + 2][arow] = av.z;
        As[acol + 3][arow] = av.w;
        *reinterpret_cast<float4*>(&Bs[brow][bcol]) =
            *reinterpret_cast<const float4*>(Bp + (size_t)(k0 + brow) * DFFN + bcol);
        __syncthreads();
#pragma unroll
        for (int kk = 0; kk < BK; ++kk) {
            float ra[TM], rb[TN];
            *reinterpret_cast<float4*>(ra)     = *reinterpret_cast<const float4*>(&As[kk][ty * TM]);
            *reinterpret_cast<float4*>(ra + 4) = *reinterpret_cast<const float4*>(&As[kk][ty * TM + 4]);
            *reinterpret_cast<float4*>(rb)     = *reinterpret_cast<const float4*>(&Bs[kk][tx * TN]);
            *reinterpret_cast<float4*>(rb + 4) = *reinterpret_cast<const float4*>(&Bs[kk][tx * TN + 4]);
#pragma unroll
            for (int i = 0; i < TM; ++i)
#pragma unroll
                for (int j = 0; j < TN; ++j)
                    acc[i][j] += ra[i] * rb[j];
        }
        __syncthreads();
    }

    int n0 = nt * BN + tx * TN;
    float bias[TN];
    *reinterpret_cast<float4*>(bias)     = *reinterpret_cast<const float4*>(b1 + n0);
    *reinterpret_cast<float4*>(bias + 4) = *reinterpret_cast<const float4*>(b1 + n0 + 4);
#pragma unroll
    for (int i = 0; i < TM; ++i) {
        int m = mt * BM + ty * TM + i;
        float* hp = g_h + (size_t)m * DFFN + n0;
        float v[TN];
#pragma unroll
        for (int j = 0; j < TN; ++j)
            v[j] = gelu_tanh(acc[i][j] + bias[j]);
        *reinterpret_cast<float4*>(hp)     = *reinterpret_cast<float4*>(v);
        *reinterpret_cast<float4*>(hp + 4) = *reinterpret_cast<float4*>(v + 4);
    }
}

// 5) GEMM2 + bias + residual + scatter:  out[b, sel] = x[b, sel] + g_h @ w2 + b2
__global__ __launch_bounds__(256, 2)
void ffn2_kernel(const float* __restrict__ x,
                 const float* __restrict__ w2,
                 const float* __restrict__ b2,
                 float* __restrict__ out) {
    __shared__ float    As[BK][BM];
    __shared__ float    Bs[BK][BN];
    __shared__ unsigned rowtok[BM];

    int mt = blockIdx.y, nt = blockIdx.x;
    int tid = threadIdx.x;
    if (tid < BM) {
        int m = mt * BM + tid;
        int b = m / KK, j = m % KK;
        rowtok[tid] = (unsigned)(b * NN + g_sel[b * KK + j]);
    }
    __syncthreads();

    int tx = tid % 16, ty = tid / 16;
    int arow = tid >> 1, acol = (tid & 1) * 4;
    int brow = tid >> 5, bcol = (tid & 31) * 4;

    float acc[TM][TN] = {};
    const float* Ap = g_h + (size_t)(mt * BM + arow) * DFFN;
    const float* Bp = w2 + nt * BN;

    for (int k0 = 0; k0 < DFFN; k0 += BK) {
        float4 av = *reinterpret_cast<const float4*>(Ap + k0 + acol);
        As[acol + 0][arow] = av.x;
        As[acol + 1][arow] = av.y;
        As[acol + 2][arow] = av.z;
        As[acol + 3][arow] = av.w;
        *reinterpret_cast<float4*>(&Bs[brow][bcol]) =
            *reinterpret_cast<const float4*>(Bp + (size_t)(k0 + brow) * DD + bcol);
        __syncthreads();
#pragma unroll
        for (int kk = 0; kk < BK; ++kk) {
            float ra[TM], rb[TN];
            *reinterpret_cast<float4*>(ra)     = *reinterpret_cast<const float4*>(&As[kk][ty * TM]);
            *reinterpret_cast<float4*>(ra + 4) = *reinterpret_cast<const float4*>(&As[kk][ty * TM + 4]);
            *reinterpret_cast<float4*>(rb)     = *reinterpret_cast<const float4*>(&Bs[kk][tx * TN]);
            *reinterpret_cast<float4*>(rb + 4) = *reinterpret_cast<const float4*>(&Bs[kk][tx * TN + 4]);
#pragma unroll
            for (int i = 0; i < TM; ++i)
#pragma unroll
                for (int j = 0; j < TN; ++j)
                    acc[i][j] += ra[i] * rb[j];
        }
        __syncthreads();
    }

    int n0 = nt * BN + tx * TN;
    float bias[TN];
    *reinterpret_cast<float4*>(bias)     = *reinterpret_cast<const float4*>(b2 + n0);
    *reinterpret_cast<float4*>(bias + 4) = *reinterpret_cast<const float4*>(b2 + n0 + 4);
#pragma unroll
    for (int i = 0; i < TM; ++i) {
        size_t base = (size_t)rowtok[ty * TM + i] * DD + n0;
        float4 x0 = *reinterpret_cast<const float4*>(x + base);
        float4 x1 = *reinterpret_cast<const float4*>(x + base + 4);
        float v[TN];
        v[0] = x0.x + acc[i][0] + bias[0];
        v[1] = x0.y + acc[i][1] + bias[1];
        v[2] = x0.z + acc[i][2] + bias[2];
        v[3] = x0.w + acc[i][3] + bias[3];
        v[4] = x1.x + acc[i][4] + bias[4];
        v[5] = x1.y + acc[i][5] + bias[5];
        v[6] = x1.z + acc[i][6] + bias[6];
        v[7] = x1.w + acc[i][7] + bias[7];
        *reinterpret_cast<float4*>(out + base)     = *reinterpret_cast<float4*>(v);
        *reinterpret_cast<float4*>(out + base + 4) = *reinterpret_cast<float4*>(v + 4);
    }
}

// ---------------------------------------------------------------------------
// Launch: inputs are x, gate_w, w1, b1, w2, b2, k (metadata order)
// ---------------------------------------------------------------------------
extern "C" void kernel_launch(void* const* d_in, const int* in_sizes, int n_in,
                              void* d_out, int out_size) {
    const float* x  = (const float*)d_in[0];
    const float* gw = (const float*)d_in[1];
    const float* w1 = (const float*)d_in[2];
    const float* b1 = (const float*)d_in[3];
    const float* w2 = (const float*)d_in[4];
    const float* b2 = (const float*)d_in[5];
    float* out = (float*)d_out;

    // 1) gate scores: 16384 rows, one warp each -> 2048 blocks of 256
    scores_kernel<<<(BB * NN) / 8, 256>>>(x, gw);
    // 2) per-batch top-K
    topk_kernel<<<BB, 1024>>>();
    // 3) out = x
    copy_kernel<<<4096, 256>>>(x, out);
    // 4) h = gelu(x_sel @ w1 + b1)
    ffn1_kernel<<<dim3(DFFN / BN, MM / BM), 256>>>(x, w1, b1);
    // 5) out[sel] = x_sel + h @ w2 + b2
    ffn2_kernel<<<dim3(DD / BN, MM / BM), 256>>>(x, w2, b2, out);
}

// round 2
// speedup vs baseline: 1.0014x; 1.0014x over previous
#include <cuda_runtime.h>
#include <math.h>

// Problem constants (MoDRouter_48387101556956: fixed shapes)
#define BB   4
#define NN   4096
#define DD   1024
#define DFFN 4096
#define KK   2048
#define MM   (BB * KK)   // 8192 selected tokens total

// ---------------------------------------------------------------------------
// Device scratch (no allocations allowed in kernel_launch)
// ---------------------------------------------------------------------------
__device__ float g_scores[BB * NN];
__device__ int   g_sel[BB * KK];                    // selected token index (0..NN-1) per batch
__device__ float g_h[(size_t)MM * DFFN];            // GELU(x_sel @ w1 + b1), 128 MiB

// ---------------------------------------------------------------------------
// 1) Gate scores: scores[b,n] = dot(x[b,n,:], gate_w)  — one warp per row
// ---------------------------------------------------------------------------
__global__ void scores_kernel(const float* __restrict__ x,
                              const float* __restrict__ gw) {
    int gwarp = (blockIdx.x * blockDim.x + threadIdx.x) >> 5;
    int lane  = threadIdx.x & 31;
    if (gwarp >= BB * NN) return;
    const float4* xr = reinterpret_cast<const float4*>(x + (size_t)gwarp * DD);
    const float4* g4 = reinterpret_cast<const float4*>(gw);
    float s = 0.0f;
#pragma unroll
    for (int i = 0; i < DD / 4 / 32; ++i) {   // 8 float4 per lane
        float4 a = xr[lane + i * 32];
        float4 b = g4[lane + i * 32];
        s += a.x * b.x + a.y * b.y + a.z * b.z + a.w * b.w;
    }
#pragma unroll
    for (int o = 16; o; o >>= 1) s += __shfl_xor_sync(0xFFFFFFFFu, s, o);
    if (lane == 0) g_scores[gwarp] = s;
}

// ---------------------------------------------------------------------------
// 2) Per-batch top-K: bitonic sort 4096 (score,idx) pairs in smem (ascending),
//    take the last K indices. Order within the set is irrelevant downstream.
// ---------------------------------------------------------------------------
__global__ void topk_kernel() {
    __shared__ float key[NN];
    __shared__ int   val[NN];
    int b = blockIdx.x;
    for (int i = threadIdx.x; i < NN; i += blockDim.x) {
        key[i] = g_scores[b * NN + i];
        val[i] = i;
    }
    __syncthreads();
    for (int k = 2; k <= NN; k <<= 1) {
        for (int j = k >> 1; j > 0; j >>= 1) {
            for (int i = threadIdx.x; i < NN; i += blockDim.x) {
                int ixj = i ^ j;
                if (ixj > i) {
                    bool up = ((i & k) == 0);
                    float ki = key[i], kj = key[ixj];
                    bool do_swap = up ? (ki > kj) : (ki < kj);
                    if (do_swap) {
                        key[i] = kj; key[ixj] = ki;
                        int t = val[i]; val[i] = val[ixj]; val[ixj] = t;
                    }
                }
            }
            __syncthreads();
        }
    }
    for (int i = threadIdx.x; i < KK; i += blockDim.x)
        g_sel[b * KK + i] = val[NN - 1 - i];
}

// ---------------------------------------------------------------------------
// 3) out = x (full copy); selected rows get overwritten by ffn2 scatter
// ---------------------------------------------------------------------------
__global__ void copy_kernel(const float* __restrict__ x, float* __restrict__ out) {
    size_t n4 = (size_t)BB * NN * DD / 4;
    const float4* src = reinterpret_cast<const float4*>(x);
    float4*       dst = reinterpret_cast<float4*>(out);
    for (size_t i = blockIdx.x * (size_t)blockDim.x + threadIdx.x; i < n4;
         i += (size_t)gridDim.x * blockDim.x)
        dst[i] = src[i];
}

// ---------------------------------------------------------------------------
// SGEMM tiling: 128x128 block tile, K=8 step, 256 threads, 8x8 micro-tile
// ---------------------------------------------------------------------------
#define BM 128
#define BN 128
#define BK 8
#define TM 8
#define TN 8

__device__ __forceinline__ float gelu_tanh(float u) {
    float t = tanhf(0.7978845608028654f * (u + 0.044715f * u * u * u));
    return 0.5f * u * (1.0f + t);
}

// 4) GEMM1 (gathered A) + bias + GELU:  g_h = gelu(x[sel] @ w1 + b1)
__global__ __launch_bounds__(256, 2)
void ffn1_kernel(const float* __restrict__ x,
                 const float* __restrict__ w1,
                 const float* __restrict__ b1) {
    __shared__ float    As[BK][BM];
    __shared__ float    Bs[BK][BN];
    __shared__ unsigned rowtok[BM];   // (b*NN + tok) for each local row

    int mt = blockIdx.y, nt = blockIdx.x;
    int tid = threadIdx.x;
    if (tid < BM) {
        int m = mt * BM + tid;
        int b = m / KK, j = m % KK;
        rowtok[tid] = (unsigned)(b * NN + g_sel[b * KK + j]);
    }
    __syncthreads();

    int tx = tid % 16, ty = tid / 16;
    int arow = tid >> 1, acol = (tid & 1) * 4;
    int brow = tid >> 5, bcol = (tid & 31) * 4;

    float acc[TM][TN] = {};
    const float* Bp = w1 + nt * BN;
    size_t abase = (size_t)rowtok[arow] * DD;

    for (int k0 = 0; k0 < DD; k0 += BK) {
        float4 av = *reinterpret_cast<const float4*>(x + abase + k0 + acol);
        As[acol + 0][arow] = av.x;
        As[acol + 1][arow] = av.y;
        As[acol + 2][arow] = av.z;
        As[acol + 3][arow] = av.w;
        *reinterpret_cast<float4*>(&Bs[brow][bcol]) =
            *reinterpret_cast<const float4*>(Bp + (size_t)(k0 + brow) * DFFN + bcol);
        __syncthreads();
#pragma unroll
        for (int kk = 0; kk < BK; ++kk) {
            float ra[TM], rb[TN];
            *reinterpret_cast<float4*>(ra)     = *reinterpret_cast<const float4*>(&As[kk][ty * TM]);
            *reinterpret_cast<float4*>(ra + 4) = *reinterpret_cast<const float4*>(&As[kk][ty * TM + 4]);
            *reinterpret_cast<float4*>(rb)     = *reinterpret_cast<const float4*>(&Bs[kk][tx * TN]);
            *reinterpret_cast<float4*>(rb + 4) = *reinterpret_cast<const float4*>(&Bs[kk][tx * TN + 4]);
#pragma unroll
            for (int i = 0; i < TM; ++i)
#pragma unroll
                for (int j = 0; j < TN; ++j)
                    acc[i][j] += ra[i] * rb[j];
        }
        __syncthreads();
    }

    int n0 = nt * BN + tx * TN;
    float bias[TN];
    *reinterpret_cast<float4*>(bias)     = *reinterpret_cast<const float4*>(b1 + n0);
    *reinterpret_cast<float4*>(bias + 4) = *reinterpret_cast<const float4*>(b1 + n0 + 4);
#pragma unroll
    for (int i = 0; i < TM; ++i) {
        int m = mt * BM + ty * TM + i;
        float* hp = g_h + (size_t)m * DFFN + n0;
        float v[TN];
#pragma unroll
        for (int j = 0; j < TN; ++j)
            v[j] = gelu_tanh(acc[i][j] + bias[j]);
        *reinterpret_cast<float4*>(hp)     = *reinterpret_cast<float4*>(v);
        *reinterpret_cast<float4*>(hp + 4) = *reinterpret_cast<float4*>(v + 4);
    }
}

// 5) GEMM2 + bias + residual + scatter:  out[b, sel] = x[b, sel] + g_h @ w2 + b2
__global__ __launch_bounds__(256, 2)
void ffn2_kernel(const float* __restrict__ x,
                 const float* __restrict__ w2,
                 const float* __restrict__ b2,
                 float* __restrict__ out) {
    __shared__ float    As[BK][BM];
    __shared__ float    Bs[BK][BN];
    __shared__ unsigned rowtok[BM];

    int mt = blockIdx.y, nt = blockIdx.x;
    int tid = threadIdx.x;
    if (tid < BM) {
        int m = mt * BM + tid;
        int b = m / KK, j = m % KK;
        rowtok[tid] = (unsigned)(b * NN + g_sel[b * KK + j]);
    }
    __syncthreads();

    int tx = tid % 16, ty = tid / 16;
    int arow = tid >> 1, acol = (tid & 1) * 4;
    int brow = tid >> 5, bcol = (tid & 31) * 4;

    float acc[TM][TN] = {};
    const float* Ap = g_h + (size_t)(mt * BM + arow) * DFFN;
    const float* Bp = w2 + nt * BN;

    for (int k0 = 0; k0 < DFFN; k0 += BK) {
        float4 av = *reinterpret_cast<const float4*>(Ap + k0 + acol);
        As[acol + 0][arow] = av.x;
        As[acol + 1][arow] = av.y;
        As[acol + 2][arow] = av.z;
        As[acol + 3][arow] = av.w;
        *reinterpret_cast<float4*>(&Bs[brow][bcol]) =
            *reinterpret_cast<const float4*>(Bp + (size_t)(k0 + brow) * DD + bcol);
        __syncthreads();
#pragma unroll
        for (int kk = 0; kk < BK; ++kk) {
            float ra[TM], rb[TN];
            *reinterpret_cast<float4*>(ra)     = *reinterpret_cast<const float4*>(&As[kk][ty * TM]);
            *reinterpret_cast<float4*>(ra + 4) = *reinterpret_cast<const float4*>(&As[kk][ty * TM + 4]);
            *reinterpret_cast<float4*>(rb)     = *reinterpret_cast<const float4*>(&Bs[kk][tx * TN]);
            *reinterpret_cast<float4*>(rb + 4) = *reinterpret_cast<const float4*>(&Bs[kk][tx * TN + 4]);
#pragma unroll
            for (int i = 0; i < TM; ++i)
#pragma unroll
                for (int j = 0; j < TN; ++j)
                    acc[i][j] += ra[i] * rb[j];
        }
        __syncthreads();
    }

    int n0 = nt * BN + tx * TN;
    float bias[TN];
    *reinterpret_cast<float4*>(bias)     = *reinterpret_cast<const float4*>(b2 + n0);
    *reinterpret_cast<float4*>(bias + 4) = *reinterpret_cast<const float4*>(b2 + n0 + 4);
#pragma unroll
    for (int i = 0; i < TM; ++i) {
        size_t base = (size_t)rowtok[ty * TM + i] * DD + n0;
        float4 x0 = *reinterpret_cast<const float4*>(x + base);
        float4 x1 = *reinterpret_cast<const float4*>(x + base + 4);
        float v[TN];
        v[0] = x0.x + acc[i][0] + bias[0];
        v[1] = x0.y + acc[i][1] + bias[1];
        v[2] = x0.z + acc[i][2] + bias[2];
        v[3] = x0.w + acc[i][3] + bias[3];
        v[4] = x1.x + acc[i][4] + bias[4];
        v[5] = x1.y + acc[i][5] + bias[5];
        v[6] = x1.z + acc[i][6] + bias[6];
        v[7] = x1.w + acc[i][7] + bias[7];
        *reinterpret_cast<float4*>(out + base)     = *reinterpret_cast<float4*>(v);
        *reinterpret_cast<float4*>(out + base + 4) = *reinterpret_cast<float4*>(v + 4);
    }
}

// ---------------------------------------------------------------------------
// Launch: inputs are x, gate_w, w1, b1, w2, b2, k (metadata order)
// ---------------------------------------------------------------------------
extern "C" void kernel_launch(void* const* d_in, const int* in_sizes, int n_in,
                              void* d_out, int out_size) {
    const float* x  = (const float*)d_in[0];
    const float* gw = (const float*)d_in[1];
    const float* w1 = (const float*)d_in[2];
    const float* b1 = (const float*)d_in[3];
    const float* w2 = (const float*)d_in[4];
    const float* b2 = (const float*)d_in[5];
    float* out = (float*)d_out;

    // 1) gate scores: 16384 rows, one warp each -> 2048 blocks of 256
    scores_kernel<<<(BB * NN) / 8, 256>>>(x, gw);
    // 2) per-batch top-K
    topk_kernel<<<BB, 1024>>>();
    // 3) out = x
    copy_kernel<<<4096, 256>>>(x, out);
    // 4) h = gelu(x_sel @ w1 + b1)
    ffn1_kernel<<<dim3(DFFN / BN, MM / BM), 256>>>(x, w1, b1);
    // 5) out[sel] = x_sel + h @ w2 + b2
    ffn2_kernel<<<dim3(DD / BN, MM / BM), 256>>>(x, w2, b2, out);
}